// round 1
// baseline (speedup 1.0000x reference)
#include <cuda_runtime.h>
#include <math.h>

// Problem constants (compile-time known from reference)
#define E_       8          // experts
#define NTOK     8192       // B*T = 4*2048
#define D_       1024
#define F_       2816
#define NSLOT    (NTOK * 2) // 16384 total (token, expert) assignments
#define SLOT_PAD 16896      // 16384 + 8*64 padding (each expert range 64-aligned)
#define OUT_ELEMS (NTOK * D_)

#define BM 64
#define BN 64
#define BK 16

// ---------------- scratch (static device globals; no runtime allocation) ---
__device__ float g_act[(size_t)SLOT_PAD * F_];   // SwiGLU activations, ~190 MB
__device__ int   g_perm_token[SLOT_PAD];         // slot -> token (-1 = pad)
__device__ float g_perm_w[SLOT_PAD];             // slot -> routing weight
__device__ int   g_counts[E_];
__device__ int   g_cursor[E_];
__device__ int   g_pad_off[E_ + 1];              // 64-aligned expert offsets
__device__ int   g_topk_idx[NSLOT];
__device__ float g_topk_w[NSLOT];

// ---------------- init: zero output (it is poisoned), reset bookkeeping ----
__global__ void init_kernel(float* __restrict__ out) {
    int i = blockIdx.x * blockDim.x + threadIdx.x;
    if (i < OUT_ELEMS) out[i] = 0.0f;
    if (i < SLOT_PAD)  g_perm_token[i] = -1;
    if (i < E_)        g_counts[i] = 0;
}

// ---------------- router: fp64-accumulated scores, softmax, top-2 ----------
__global__ void router_kernel(const float* __restrict__ x,
                              const float* __restrict__ rw) {
    int t = blockIdx.x;
    const float* xr = x + (size_t)t * D_;
    int lane = threadIdx.x & 31;
    int w    = threadIdx.x >> 5;   // one warp per expert (8 warps)

    double s = 0.0;
    for (int d = lane; d < D_; d += 32)
        s += (double)xr[d] * (double)rw[d * E_ + w];
    #pragma unroll
    for (int o = 16; o > 0; o >>= 1)
        s += __shfl_down_sync(0xffffffffu, s, o);

    __shared__ double sc[E_];
    if (lane == 0) sc[w] = s;
    __syncthreads();

    if (threadIdx.x == 0) {
        double m = sc[0];
        #pragma unroll
        for (int e = 1; e < E_; e++) m = fmax(m, sc[e]);
        double p[E_], sum = 0.0;
        #pragma unroll
        for (int e = 0; e < E_; e++) { p[e] = exp(sc[e] - m); sum += p[e]; }
        #pragma unroll
        for (int e = 0; e < E_; e++) p[e] /= sum;

        // top-2, ties -> lower index first (matches jax.lax.top_k)
        int i0 = 0;
        #pragma unroll
        for (int e = 1; e < E_; e++) if (p[e] > p[i0]) i0 = e;
        int i1 = (i0 == 0) ? 1 : 0;
        #pragma unroll
        for (int e = 0; e < E_; e++) {
            if (e == i0) continue;
            if (p[e] > p[i1]) i1 = e;
        }
        float p0 = (float)p[i0], p1 = (float)p[i1];
        float inv = 1.0f / (p0 + p1);
        g_topk_idx[t * 2 + 0] = i0;
        g_topk_idx[t * 2 + 1] = i1;
        g_topk_w[t * 2 + 0] = p0 * inv;
        g_topk_w[t * 2 + 1] = p1 * inv;
        atomicAdd(&g_counts[i0], 1);
        atomicAdd(&g_counts[i1], 1);
    }
}

// ---------------- tiny scan: 64-aligned expert offsets ---------------------
__global__ void scan_kernel() {
    int off = 0;
    #pragma unroll
    for (int e = 0; e < E_; e++) {
        g_pad_off[e] = off;
        g_cursor[e]  = off;
        off += (g_counts[e] + 63) & ~63;
    }
    g_pad_off[E_] = off;
}

// ---------------- fill permutation (order-independent result) --------------
__global__ void fill_kernel() {
    int idx = blockIdx.x * blockDim.x + threadIdx.x;
    if (idx >= NSLOT) return;
    int e    = g_topk_idx[idx];
    int slot = atomicAdd(&g_cursor[e], 1);
    g_perm_token[slot] = idx >> 1;
    g_perm_w[slot]     = g_topk_w[idx];
}

// ---------------- GEMM1: act = silu(x@G) * (x@U), gathered rows ------------
__global__ __launch_bounds__(256)
void gemm1_kernel(const float* __restrict__ x,
                  const float* __restrict__ gate_w,
                  const float* __restrict__ up_w) {
    int row0 = blockIdx.y * BM;
    if (row0 >= g_pad_off[E_]) return;   // fully in unused tail

    int e = 0;
    while (e < E_ - 1 && g_pad_off[e + 1] <= row0) e++;
    const float* G = gate_w + (size_t)e * D_ * F_;
    const float* U = up_w   + (size_t)e * D_ * F_;
    int n0 = blockIdx.x * BN;

    __shared__ float As[BK][BM + 4];
    __shared__ float Bg[BK][BN];
    __shared__ float Bu[BK][BN];

    int tid   = threadIdx.x;
    int a_row = tid >> 2;            // 0..63
    int a_k   = (tid & 3) * 4;       // 0,4,8,12
    int tok   = g_perm_token[row0 + a_row];
    bool valid = (tok >= 0);
    const float* xrow = x + (size_t)(valid ? tok : 0) * D_;

    int b_k = tid >> 4;              // 0..15
    int b_n = (tid & 15) * 4;        // 0..60

    int ty = tid >> 4;               // 0..15 (m)
    int tx = tid & 15;               // 0..15 (n)

    float ag[4][4] = {};
    float au[4][4] = {};

    for (int k0 = 0; k0 < D_; k0 += BK) {
        float4 av = valid ? *(const float4*)(xrow + k0 + a_k)
                          : make_float4(0.f, 0.f, 0.f, 0.f);
        As[a_k + 0][a_row] = av.x;
        As[a_k + 1][a_row] = av.y;
        As[a_k + 2][a_row] = av.z;
        As[a_k + 3][a_row] = av.w;
        *(float4*)&Bg[b_k][b_n] = *(const float4*)(G + (size_t)(k0 + b_k) * F_ + n0 + b_n);
        *(float4*)&Bu[b_k][b_n] = *(const float4*)(U + (size_t)(k0 + b_k) * F_ + n0 + b_n);
        __syncthreads();

        #pragma unroll
        for (int kk = 0; kk < BK; kk++) {
            float4 a4 = *(const float4*)&As[kk][ty * 4];
            float4 g4 = *(const float4*)&Bg[kk][tx * 4];
            float4 u4 = *(const float4*)&Bu[kk][tx * 4];
            float am[4] = {a4.x, a4.y, a4.z, a4.w};
            float gm[4] = {g4.x, g4.y, g4.z, g4.w};
            float um[4] = {u4.x, u4.y, u4.z, u4.w};
            #pragma unroll
            for (int i = 0; i < 4; i++)
                #pragma unroll
                for (int j = 0; j < 4; j++) {
                    ag[i][j] += am[i] * gm[j];
                    au[i][j] += am[i] * um[j];
                }
        }
        __syncthreads();
    }

    #pragma unroll
    for (int i = 0; i < 4; i++) {
        int r = row0 + ty * 4 + i;
        float* arow = g_act + (size_t)r * F_ + n0 + tx * 4;
        #pragma unroll
        for (int j = 0; j < 4; j++) {
            float g = ag[i][j], u = au[i][j];
            float sv = g / (1.0f + __expf(-g));   // silu
            arow[j] = sv * u;
        }
    }
}

// ---------------- GEMM2: out[tok] += w * (act @ Wdown) ---------------------
__global__ __launch_bounds__(256)
void gemm2_kernel(const float* __restrict__ down_w,
                  float* __restrict__ out) {
    int row0 = blockIdx.y * BM;
    if (row0 >= g_pad_off[E_]) return;

    int e = 0;
    while (e < E_ - 1 && g_pad_off[e + 1] <= row0) e++;
    const float* Wd = down_w + (size_t)e * F_ * D_;
    int n0 = blockIdx.x * BN;

    __shared__ float As[BK][BM + 4];
    __shared__ float Bs[BK][BN];

    int tid   = threadIdx.x;
    int a_row = tid >> 2;
    int a_k   = (tid & 3) * 4;
    const float* arow_g = g_act + (size_t)(row0 + a_row) * F_;

    int b_k = tid >> 4;
    int b_n = (tid & 15) * 4;
    int ty = tid >> 4;
    int tx = tid & 15;

    float acc[4][4] = {};

    for (int k0 = 0; k0 < F_; k0 += BK) {
        float4 av = *(const float4*)(arow_g + k0 + a_k);
        As[a_k + 0][a_row] = av.x;
        As[a_k + 1][a_row] = av.y;
        As[a_k + 2][a_row] = av.z;
        As[a_k + 3][a_row] = av.w;
        *(float4*)&Bs[b_k][b_n] = *(const float4*)(Wd + (size_t)(k0 + b_k) * D_ + n0 + b_n);
        __syncthreads();

        #pragma unroll
        for (int kk = 0; kk < BK; kk++) {
            float4 a4 = *(const float4*)&As[kk][ty * 4];
            float4 b4 = *(const float4*)&Bs[kk][tx * 4];
            float am[4] = {a4.x, a4.y, a4.z, a4.w};
            float bm[4] = {b4.x, b4.y, b4.z, b4.w};
            #pragma unroll
            for (int i = 0; i < 4; i++)
                #pragma unroll
                for (int j = 0; j < 4; j++)
                    acc[i][j] += am[i] * bm[j];
        }
        __syncthreads();
    }

    #pragma unroll
    for (int i = 0; i < 4; i++) {
        int r = row0 + ty * 4 + i;
        int tok = g_perm_token[r];
        if (tok < 0) continue;
        float wgt = g_perm_w[r];
        float* orow = out + (size_t)tok * D_ + n0 + tx * 4;
        #pragma unroll
        for (int j = 0; j < 4; j++)
            atomicAdd(&orow[j], acc[i][j] * wgt);  // exactly 2 adds/elem: order-invariant
    }
}

// ---------------- launch ----------------------------------------------------
extern "C" void kernel_launch(void* const* d_in, const int* in_sizes, int n_in,
                              void* d_out, int out_size) {
    const float* x      = (const float*)d_in[0];
    const float* rw     = (const float*)d_in[1];
    const float* gate_w = (const float*)d_in[2];
    const float* up_w   = (const float*)d_in[3];
    const float* down_w = (const float*)d_in[4];
    float* out = (float*)d_out;

    init_kernel<<<(OUT_ELEMS + 255) / 256, 256>>>(out);
    router_kernel<<<NTOK, 256>>>(x, rw);
    scan_kernel<<<1, 1>>>();
    fill_kernel<<<(NSLOT + 255) / 256, 256>>>();

    dim3 g1(F_ / BN, SLOT_PAD / BM);   // 44 x 264
    gemm1_kernel<<<g1, 256>>>(x, gate_w, up_w);

    dim3 g2(D_ / BN, SLOT_PAD / BM);   // 16 x 264
    gemm2_kernel<<<g2, 256>>>(down_w, out);
}